// round 2
// baseline (speedup 1.0000x reference)
#include <cuda_runtime.h>

#define N_STFT 1025
#define SP     1028        // padded spec/buf row stride (16B-aligned rows)
#define NMEL   128
#define NTIME  1024
#define NBT    4096
#define TILE_R 16
#define NTHR   256
#define NCTAS  (NBT / TILE_R)   // 256
#define NCHUNK 9                // ceil(1025/128)
#define NITER  20

#define LRc    0.3f
#define MOMc   0.9f
#define INVc   (2.0f / 4096.0f)

// shared memory layout (floats)
#define FB_STRIDE   132
#define SPT_STRIDE  18
#define DS_STRIDE   132
#define OFF_FB   0
#define OFF_SPT  (128 * FB_STRIDE)               // 16896
#define OFF_DS   (OFF_SPT + 128 * SPT_STRIDE)    // 19200
#define OFF_MEL  (OFF_DS + TILE_R * DS_STRIDE)   // 21312
#define SMEM_FLOATS (OFF_MEL + TILE_R * NMEL)    // 23360 floats = 93440 B

typedef unsigned long long u64;

// scratch: working spectrogram + momentum buffer (rows padded to SP, pads stay 0)
__device__ float g_spec[(size_t)NBT * SP];
__device__ float g_buf [(size_t)NBT * SP];

__device__ __forceinline__ u64 dup2(float x) {
    u64 r; asm("mov.b64 %0, {%1, %1};" : "=l"(r) : "f"(x)); return r;
}
__device__ __forceinline__ float2 unpk(u64 v) {
    float2 f; asm("mov.b64 {%0, %1}, %2;" : "=f"(f.x), "=f"(f.y) : "l"(v)); return f;
}
__device__ __forceinline__ void ffma2(u64& d, u64 a, u64 b) {
    asm("fma.rn.f32x2 %0, %1, %2, %0;" : "+l"(d) : "l"(a), "l"(b));
}

__global__ void __launch_bounds__(NTHR, 2)
imel_kernel(const float* __restrict__ mel_in,     // (B, M, T)
            const float* __restrict__ spec_init,  // (B, T, F)
            const float* __restrict__ fb,         // (F, M)
            float* __restrict__ out)              // (B, F, T)
{
    extern __shared__ float sm[];
    float* fbu   = sm + OFF_FB;    // [128][132] fb chunk
    float* specT = sm + OFF_SPT;   // [128][18]  spec chunk transposed [f][r]
    float* dsm   = sm + OFF_DS;    // [16][132]  diff [r][m]
    float* mels  = sm + OFF_MEL;   // [16][128]  mel rows [r][m]

    const int tid  = threadIdx.x;
    const int lane = tid & 31;
    const int rg   = tid >> 5;          // 0..7
    const int r0   = rg * 2;
    const int m4   = lane * 4;
    const int row0 = blockIdx.x * TILE_R;
    const int b    = row0 / NTIME;
    const int t0   = row0 & (NTIME - 1);

    // ---- init this CTA's spec/buf rows (pad cols set to 0, stay 0 forever) ----
    for (int idx = tid; idx < TILE_R * SP; idx += NTHR) {
        int r = idx / SP;
        int f = idx - r * SP;
        int g = (row0 + r) * SP + f;
        g_spec[g] = (f < N_STFT) ? spec_init[(row0 + r) * N_STFT + f] : 0.0f;
        g_buf[g]  = 0.0f;
    }
    // ---- mel transpose into smem: mels[j][m] = mel_in[b][m][t0+j] ----
    for (int idx = tid; idx < TILE_R * NMEL; idx += NTHR) {
        int m = idx >> 4;
        int j = idx & 15;
        mels[j * NMEL + m] = mel_in[(b * NMEL + m) * NTIME + t0 + j];
    }
    __syncthreads();

    for (int it = 0; it < NITER; ++it) {
        // ================= GEMM1: acc[r][m] = spec @ fb =================
        u64 a0l = 0, a0h = 0, a1l = 0, a1h = 0;  // (r0,m01)(r0,m23)(r1,m01)(r1,m23)
        for (int fc = 0; fc < NCHUNK * 128; fc += 128) {
            // stage fb chunk [fl][m] (zero-filled past F)
            for (int i = tid * 4; i < 128 * 128; i += NTHR * 4) {
                int fl = i >> 7, mm = i & 127;
                int f = fc + fl;
                float4 v = make_float4(0.f, 0.f, 0.f, 0.f);
                if (f < N_STFT) v = *(const float4*)&fb[f * NMEL + mm];
                *(float4*)&fbu[fl * FB_STRIDE + mm] = v;
            }
            // stage spec chunk transposed: specT[fl][r]
            for (int idx = tid; idx < TILE_R * 128; idx += NTHR) {
                int r = idx >> 7, fl = idx & 127;
                int f = fc + fl;
                specT[fl * SPT_STRIDE + r] = (f < SP) ? g_spec[(row0 + r) * SP + f] : 0.0f;
            }
            __syncthreads();
            #pragma unroll 8
            for (int fl = 0; fl < 128; ++fl) {
                float2 sp = *(const float2*)&specT[fl * SPT_STRIDE + r0];
                ulonglong2 fv = *(const ulonglong2*)&fbu[fl * FB_STRIDE + m4];
                u64 S0 = dup2(sp.x), S1 = dup2(sp.y);
                ffma2(a0l, fv.x, S0); ffma2(a0h, fv.y, S0);
                ffma2(a1l, fv.x, S1); ffma2(a1h, fv.y, S1);
            }
            __syncthreads();
        }
        // ---- diff = mel - acc -> dsm[r][m] ----
        {
            float2 A0l = unpk(a0l), A0h = unpk(a0h), A1l = unpk(a1l), A1h = unpk(a1h);
            float4 mv0 = *(const float4*)&mels[r0 * NMEL + m4];
            float4 mv1 = *(const float4*)&mels[(r0 + 1) * NMEL + m4];
            *(float4*)&dsm[r0 * DS_STRIDE + m4] =
                make_float4(mv0.x - A0l.x, mv0.y - A0l.y, mv0.z - A0h.x, mv0.w - A0h.y);
            *(float4*)&dsm[(r0 + 1) * DS_STRIDE + m4] =
                make_float4(mv1.x - A1l.x, mv1.y - A1l.y, mv1.z - A1h.x, mv1.w - A1h.y);
        }
        // (dsm writes ordered before reads by the __syncthreads inside GEMM2 staging)

        // ================= GEMM2 + momentum update =================
        for (int fc = 0; fc < NCHUNK * 128; fc += 128) {
            for (int i = tid * 4; i < 128 * 128; i += NTHR * 4) {
                int fl = i >> 7, mm = i & 127;
                int f = fc + fl;
                float4 v = make_float4(0.f, 0.f, 0.f, 0.f);
                if (f < N_STFT) v = *(const float4*)&fb[f * NMEL + mm];
                *(float4*)&fbu[fl * FB_STRIDE + mm] = v;
            }
            __syncthreads();

            u64 acc0[4] = {0, 0, 0, 0};   // row r0,   f = fc + lane + 32k, packed over m-pairs
            u64 acc1[4] = {0, 0, 0, 0};   // row r0+1
            #pragma unroll 2
            for (int mb = 0; mb < 128; mb += 4) {
                ulonglong2 d0 = *(const ulonglong2*)&dsm[r0 * DS_STRIDE + mb];
                ulonglong2 d1 = *(const ulonglong2*)&dsm[(r0 + 1) * DS_STRIDE + mb];
                #pragma unroll
                for (int k = 0; k < 4; ++k) {
                    ulonglong2 fv = *(const ulonglong2*)&fbu[(lane + 32 * k) * FB_STRIDE + mb];
                    ffma2(acc0[k], d0.x, fv.x); ffma2(acc0[k], d0.y, fv.y);
                    ffma2(acc1[k], d1.x, fv.x); ffma2(acc1[k], d1.y, fv.y);
                }
            }
            // pointwise update: buf = MOM*buf + grad ; spec = max(spec - LR*buf, 0)
            #pragma unroll
            for (int k = 0; k < 4; ++k) {
                int f = fc + lane + 32 * k;
                if (f < N_STFT) {
                    float2 g0 = unpk(acc0[k]);
                    float2 g1 = unpk(acc1[k]);
                    float gr0 = -INVc * (g0.x + g0.y);
                    float gr1 = -INVc * (g1.x + g1.y);
                    int ix0 = (row0 + r0) * SP + f;
                    int ix1 = ix0 + SP;
                    float bv0 = MOMc * g_buf[ix0] + gr0;
                    float bv1 = MOMc * g_buf[ix1] + gr1;
                    g_buf[ix0] = bv0;
                    g_buf[ix1] = bv1;
                    g_spec[ix0] = fmaxf(g_spec[ix0] - LRc * bv0, 0.0f);
                    g_spec[ix1] = fmaxf(g_spec[ix1] - LRc * bv1, 0.0f);
                }
            }
            __syncthreads();
        }
    }

    // ================= output transpose: out[b][f][t0..t0+15] =================
    for (int f = tid; f < N_STFT; f += NTHR) {
        float v[TILE_R];
        #pragma unroll
        for (int j = 0; j < TILE_R; ++j) v[j] = g_spec[(row0 + j) * SP + f];
        float* op = out + ((size_t)b * N_STFT + f) * NTIME + t0;
        #pragma unroll
        for (int j = 0; j < TILE_R; j += 4)
            *(float4*)&op[j] = make_float4(v[j], v[j + 1], v[j + 2], v[j + 3]);
    }
}

extern "C" void kernel_launch(void* const* d_in, const int* in_sizes, int n_in,
                              void* d_out, int out_size)
{
    const float* mel_in    = (const float*)d_in[0];  // melspec  (4,128,1024)
    const float* spec_init = (const float*)d_in[1];  // spec_init(4,1024,1025)
    const float* fb        = (const float*)d_in[2];  // fb       (1025,128)
    float* out             = (float*)d_out;          // (4,1025,1024) fp32

    size_t smem = SMEM_FLOATS * sizeof(float);
    cudaFuncSetAttribute(imel_kernel, cudaFuncAttributeMaxDynamicSharedMemorySize, (int)smem);
    imel_kernel<<<NCTAS, NTHR, smem>>>(mel_in, spec_init, fb, out);
}

// round 5
// speedup vs baseline: 4.0565x; 4.0565x over previous
#include <cuda_runtime.h>

#define N_STFT 1025
#define NMEL   128
#define NTIME  1024
#define NBT    4096
#define R      16
#define NTHR   256
#define NCTAS  (NBT / R)          // 256
#define NITER  20

#define LRc    0.3f
#define MOMc   0.9f
#define INVc   (2.0f / 4096.0f)

// smem layout (float units). SPEC_STRIDE % 32 == 16 so rows r and r+1 within a
// warp hit disjoint bank halves on the strided phase-B access pattern.
#define SPEC_STRIDE 1040
#define DIFF_STRIDE 144

#define OFF_SPEC  0
#define OFF_DIFF  (OFF_SPEC + R * SPEC_STRIDE)      // 16640
#define OFF_MEL   (OFF_DIFF + R * DIFF_STRIDE)      // 18944
#define OFF_W0    (OFF_MEL + R * NMEL)              // 20992
#define OFF_W1    (OFF_W0 + N_STFT)                 // 22017
#define OFF_M0    (OFF_W1 + N_STFT)                 // 23042
#define OFF_FS    (OFF_M0 + N_STFT)                 // 24067
#define OFF_WD    (OFF_FS + NMEL)                   // 24195
#define OFF_WOFF  (OFF_WD + NMEL)                   // 24323
#define OFF_WFLAT (OFF_WOFF + NMEL + 1)             // 24452
#define WFLAT_CAP 3072
#define SMEM_FLOATS (OFF_WFLAT + WFLAT_CAP)         // 27524 floats = 110096 B

__global__ void __launch_bounds__(NTHR, 2)
imel_kernel(const float* __restrict__ mel_in,     // (B, M, T)
            const float* __restrict__ spec_init,  // (B, T, F)
            const float* __restrict__ fb,         // (F, M)
            float* __restrict__ out)              // (B, F, T)
{
    extern __shared__ float sm[];
    float* sspec = sm + OFF_SPEC;     // [R][SPEC_STRIDE]
    float* sdiff = sm + OFF_DIFF;     // [R][DIFF_STRIDE]
    float* smel  = sm + OFF_MEL;      // [R][NMEL]
    float* sw0   = sm + OFF_W0;       // [F] first weight
    float* sw1   = sm + OFF_W1;       // [F] second weight
    int*   sm0   = (int*)(sm + OFF_M0);    // [F] first-nonzero mel index (<=126)
    int*   sfs   = (int*)(sm + OFF_FS);    // [M] support start f
    int*   swd   = (int*)(sm + OFF_WD);    // [M] support width
    int*   swoff = (int*)(sm + OFF_WOFF);  // [M+1] flat-weight offsets
    float* swf   = sm + OFF_WFLAT;         // flattened per-mel weights

    const int tid  = threadIdx.x;
    const int row0 = blockIdx.x * R;
    const int b    = row0 / NTIME;
    const int t0   = row0 & (NTIME - 1);

    // ---- load spec rows into smem (coalesced) ----
    for (int r = 0; r < R; r++)
        for (int f = tid; f < N_STFT; f += NTHR)
            sspec[r * SPEC_STRIDE + f] = spec_init[(size_t)(row0 + r) * N_STFT + f];

    // ---- mel transpose into smem: smel[r][m] = mel_in[b][m][t0+r] ----
    for (int idx = tid; idx < R * NMEL; idx += NTHR) {
        int m = idx >> 4, r = idx & (R - 1);
        smel[r * NMEL + m] = mel_in[((size_t)b * NMEL + m) * NTIME + t0 + r];
    }

    // ---- per-f sparse structure: <=2 nonzeros per fb row (triangular filters) ----
    for (int f = tid; f < N_STFT; f += NTHR) {
        const float* fr = fb + (size_t)f * NMEL;
        int fm = 0;
        while (fm < NMEL && fr[fm] <= 0.0f) fm++;   // first nonzero (or NMEL)
        int m0 = fm; if (m0 > NMEL - 2) m0 = NMEL - 2;
        sm0[f] = m0;
        sw0[f] = fr[m0];        // zero rows -> both weights 0 -> grad 0 (exact)
        sw1[f] = fr[m0 + 1];
    }

    // ---- per-mel contiguous support [fs, fs+wd) ----
    if (tid < NMEL) {
        int fs = -1, fe = -1;
        for (int f = 0; f < N_STFT; f++) {
            float v = fb[(size_t)f * NMEL + tid];
            if (v > 0.0f) { if (fs < 0) fs = f; fe = f; }
        }
        sfs[tid] = (fs < 0) ? 0 : fs;
        swd[tid] = (fs < 0) ? 0 : (fe - fs + 1);
    }
    __syncthreads();
    if (tid == 0) {
        int acc = 0;
        for (int m = 0; m < NMEL; m++) { swoff[m] = acc; acc += swd[m]; }
        swoff[NMEL] = acc;
    }
    __syncthreads();
    if (tid < NMEL) {
        int o = swoff[tid], fs = sfs[tid], wd = swd[tid];
        for (int j = 0; j < wd && (o + j) < WFLAT_CAP; j++)
            swf[o + j] = fb[(size_t)(fs + j) * NMEL + tid];
    }
    __syncthreads();

    const int r  = tid >> 4;     // row within CTA: 0..15
    const int lo = tid & 15;     // lane offset within row-group
    float* specr = sspec + r * SPEC_STRIDE;
    float* diffr = sdiff + r * DIFF_STRIDE;
    const float* melr = smel + r * NMEL;

    // momentum buffer lives in registers: f = lo + 16*j
    float buf[65];
    #pragma unroll
    for (int j = 0; j < 65; j++) buf[j] = 0.0f;

    for (int it = 0; it < NITER; it++) {
        // ===== phase A: diff[r][m] = mel - sum_{f in supp(m)} spec[f]*fb[f,m] =====
        #pragma unroll
        for (int j = 0; j < 8; j++) {
            int m = lo + 16 * j;                 // consecutive mels across warp
            float acc = melr[m];
            int fs = sfs[m], wd = swd[m], o = swoff[m];
            #pragma unroll 4
            for (int i = 0; i < wd; i++)
                acc -= specr[fs + i] * swf[o + i];
            diffr[m] = acc;
        }
        __syncthreads();

        // ===== phase B: grad (<=2 terms per f) + momentum + clamp =====
        #pragma unroll
        for (int j = 0; j < 65; j++) {
            int f = lo + 16 * j;
            if (j < 64 || f < N_STFT) {          // j==64 active only for lo==0 (f=1024)
                int m0 = sm0[f];
                float g  = diffr[m0] * sw0[f] + diffr[m0 + 1] * sw1[f];
                float nb = MOMc * buf[j] - INVc * g;
                buf[j] = nb;
                specr[f] = fmaxf(specr[f] - LRc * nb, 0.0f);
            }
        }
        __syncthreads();
    }

    // ===== output transpose: out[b][f][t0..t0+15] =====
    for (int f = tid; f < N_STFT; f += NTHR) {
        float v[R];
        #pragma unroll
        for (int j = 0; j < R; j++) v[j] = sspec[j * SPEC_STRIDE + f];
        float* op = out + ((size_t)b * N_STFT + f) * NTIME + t0;
        #pragma unroll
        for (int j = 0; j < R; j += 4)
            *(float4*)&op[j] = make_float4(v[j], v[j + 1], v[j + 2], v[j + 3]);
    }
}

extern "C" void kernel_launch(void* const* d_in, const int* in_sizes, int n_in,
                              void* d_out, int out_size)
{
    const float* mel_in    = (const float*)d_in[0];  // (4,128,1024)
    const float* spec_init = (const float*)d_in[1];  // (4,1024,1025)
    const float* fb        = (const float*)d_in[2];  // (1025,128)
    float* out             = (float*)d_out;          // (4,1025,1024)

    size_t smem = SMEM_FLOATS * sizeof(float);
    cudaFuncSetAttribute(imel_kernel, cudaFuncAttributeMaxDynamicSharedMemorySize, (int)smem);
    imel_kernel<<<NCTAS, NTHR, smem>>>(mel_in, spec_init, fb, out);
}

// round 6
// speedup vs baseline: 9.9677x; 2.4572x over previous
#include <cuda_runtime.h>

#define N_STFT 1025
#define NF     1024          // iterated freqs (fb row 1024 is exactly zero -> static)
#define NMEL   128
#define NTIME  1024
#define NBT    4096
#define R      16            // rows per CTA
#define TPR    16            // threads per row
#define NTHR   256
#define NCTAS  (NBT / R)     // 256
#define NITER  20
#define NPAIR  32            // f-pairs per thread (64 f each)
#define QTOT   512           // f-pairs per row

#define LRc  0.3f
#define MOMc 0.9f
#define INVc (2.0f / 4096.0f)

// ---- smem layout (float units) ----
#define OFF_SPEC 0                               // [R][512] float2 (perm slots)
#define OFF_PWA  (R * 1024)                      // 16384: [512] float2 (w0 pairs)
#define OFF_PWB  (OFF_PWA + 1024)                // 17408: [512] float2 (w1 pairs)
#define OFF_PM   (OFF_PWB + 1024)                // 18432: [512] int (m0|m0<<16)
#define OFF_DIFF (OFF_PM + 512)                  // 18944: [R][132]
#define DIFF_STRIDE 132
#define OFF_MEL  (OFF_DIFF + R * DIFF_STRIDE)    // 21056: [R][132]
#define MEL_STRIDE 132
#define OFF_A0   (OFF_MEL + R * MEL_STRIDE)      // 23168: [R][132]
#define OFF_A1   (OFF_A0 + R * 132)              // 25280: [R][132]
#define OFF_B0   (OFF_A1 + R * 132)              // 27392: [R][16]
#define OFF_B1   (OFF_B0 + R * 16)               // 27648: [R][16]
#define OFF_BT   (OFF_B1 + R * 16)               // 27904: [128] int (bthread)
#define OFF_CB   (OFF_BT + 128)                  // 28032: [16] int (contB)
#define SMEM_FLOATS (OFF_CB + 16)                // 28048 floats = 112192 B

// fused sweep: (optionally) SGD-update spec per f, and accumulate the fresh
// spec into per-segment partial sums (A = starter slots, B = continuation slot)
template <bool UPD>
__device__ __forceinline__ void sweep(float* sm, int r, int t, bool cB,
                                      float2 (&buf)[NPAIR])
{
    float2* sp2 = (float2*)(sm + OFF_SPEC) + r * 512;
    const float2* pwa = (const float2*)(sm + OFF_PWA);
    const float2* pwb = (const float2*)(sm + OFF_PWB);
    const int*    pm  = (const int*)(sm + OFF_PM);
    const float* diffr = sm + OFF_DIFF + r * DIFF_STRIDE;
    float* A0 = sm + OFF_A0 + r * 132;
    float* A1 = sm + OFF_A1 + r * 132;
    float* B0 = sm + OFF_B0 + r * 16;
    float* B1 = sm + OFF_B1 + r * 16;

    int cur = -1;
    float d0 = 0.f, d1 = 0.f, acc0 = 0.f, acc1 = 0.f;
    bool first = true;

    #pragma unroll
    for (int p = 0; p < NPAIR; ++p) {
        const int slot = p * TPR + t;
        float2 s  = sp2[slot];
        float2 wa = pwa[slot];
        float2 wb = pwb[slot];
        int mp = pm[slot];
        int m0a = mp & 0xffff;
        int m0b = mp >> 16;

        // ---- element 0 ----
        if (m0a != cur) {
            if (cur >= 0) {
                if (first & cB) { B0[t] = acc0; B1[t] = acc1; }
                else            { A0[cur] = acc0; A1[cur] = acc1; }
                first = false; acc0 = 0.f; acc1 = 0.f;
            }
            cur = m0a;
            if (UPD) { d0 = diffr[cur]; d1 = diffr[cur + 1]; }
        }
        if (UPD) {
            float g = d0 * wa.x + d1 * wb.x;
            buf[p].x = MOMc * buf[p].x - INVc * g;
            s.x = fmaxf(s.x - LRc * buf[p].x, 0.f);
        }
        acc0 = fmaf(s.x, wa.x, acc0);
        acc1 = fmaf(s.x, wb.x, acc1);

        // ---- element 1 ----
        if (m0b != cur) {
            if (first & cB) { B0[t] = acc0; B1[t] = acc1; }
            else            { A0[cur] = acc0; A1[cur] = acc1; }
            first = false; acc0 = 0.f; acc1 = 0.f;
            cur = m0b;
            if (UPD) { d0 = diffr[cur]; d1 = diffr[cur + 1]; }
        }
        if (UPD) {
            float g = d0 * wa.y + d1 * wb.y;
            buf[p].y = MOMc * buf[p].y - INVc * g;
            s.y = fmaxf(s.y - LRc * buf[p].y, 0.f);
        }
        acc0 = fmaf(s.y, wa.y, acc0);
        acc1 = fmaf(s.y, wb.y, acc1);

        if (UPD) sp2[slot] = s;
    }
    // final flush
    if (first & cB) { B0[t] = acc0; B1[t] = acc1; }
    else            { A0[cur] = acc0; A1[cur] = acc1; }
}

// combine: diff[r][m] = mel - S0(m) - S1(m-1); also re-zeroes A slots for next sweep
__device__ __forceinline__ void combine(float* sm, int tid)
{
    const int* bthr = (const int*)(sm + OFF_BT);
    #pragma unroll
    for (int k = 0; k < 8; ++k) {
        int idx = tid + k * NTHR;         // 0..2047
        int m  = idx & 127;
        int rr = idx >> 7;
        float v = sm[OFF_MEL + rr * MEL_STRIDE + m];
        float a0 = sm[OFF_A0 + rr * 132 + m];
        sm[OFF_A0 + rr * 132 + m] = 0.f;
        int bt = bthr[m];
        if (bt >= 0) a0 += sm[OFF_B0 + rr * 16 + bt];
        v -= a0;
        if (m > 0) {
            float a1 = sm[OFF_A1 + rr * 132 + (m - 1)];
            sm[OFF_A1 + rr * 132 + (m - 1)] = 0.f;
            int bt1 = bthr[m - 1];
            if (bt1 >= 0) a1 += sm[OFF_B1 + rr * 16 + bt1];
            v -= a1;
        }
        sm[OFF_DIFF + rr * DIFF_STRIDE + m] = v;
    }
}

__global__ void __launch_bounds__(NTHR, 2)
imel_kernel(const float* __restrict__ mel_in,     // (B, M, T)
            const float* __restrict__ spec_init,  // (B, T, F)
            const float* __restrict__ fb,         // (F, M)
            float* __restrict__ out)              // (B, F, T)
{
    extern __shared__ float sm[];
    const int tid  = threadIdx.x;
    const int r    = tid >> 4;     // row in CTA
    const int t    = tid & 15;     // thread within row (owns f in [64t, 64t+64))
    const int row0 = blockIdx.x * R;
    const int b    = row0 / NTIME;
    const int t0   = row0 & (NTIME - 1);

    int* pm   = (int*)(sm + OFF_PM);
    int* bthr = (int*)(sm + OFF_BT);
    int* cont = (int*)(sm + OFF_CB);
    int* tmpm0 = (int*)(sm + OFF_DIFF);   // reuse diff region during setup (2112 >= 1024)

    // ---- spec into perm layout: slot(f) = ((f&63)>>1)*16 + (f>>6), elem f&1 ----
    for (int idx = tid; idx < R * NF; idx += NTHR) {
        int rr = idx >> 10, f = idx & 1023;
        int pos = (((f & 63) >> 1) * TPR + (f >> 6)) * 2 + (f & 1);
        sm[OFF_SPEC + rr * 1024 + pos] = spec_init[(size_t)(row0 + rr) * N_STFT + f];
    }
    // ---- mel transpose ----
    for (int idx = tid; idx < R * NMEL; idx += NTHR) {
        int m = idx >> 4, rr = idx & (R - 1);
        sm[OFF_MEL + rr * MEL_STRIDE + m] =
            mel_in[((size_t)b * NMEL + m) * NTIME + t0 + rr];
    }
    // ---- per-pair sparse structure (w0,w1,m0 per f; <=2 nonzeros per fb row) ----
    for (int q = tid; q < QTOT; q += NTHR) {
        int tt = q >> 5, pp = q & 31;
        int slot = pp * TPR + tt;
        int f0 = tt * 64 + pp * 2;
        float w0v[2], w1v[2]; int m0v[2];
        #pragma unroll
        for (int e = 0; e < 2; ++e) {
            const float* fr = fb + (size_t)(f0 + e) * NMEL;
            int fm = 0;
            while (fm < NMEL && fr[fm] <= 0.0f) fm++;
            int m0 = (fm == NMEL) ? 0 : (fm > 126 ? 126 : fm);
            m0v[e] = m0;
            w0v[e] = fr[m0];
            w1v[e] = fr[m0 + 1];
            tmpm0[f0 + e] = m0;
        }
        ((float2*)(sm + OFF_PWA))[slot] = make_float2(w0v[0], w0v[1]);
        ((float2*)(sm + OFF_PWB))[slot] = make_float2(w1v[0], w1v[1]);
        pm[slot] = m0v[0] | (m0v[1] << 16);
    }
    if (tid < NMEL) bthr[tid] = -1;
    __syncthreads();
    if (tid < TPR)
        cont[tid] = (tid > 0 && tmpm0[tid * 64] == tmpm0[tid * 64 - 1]) ? 1 : 0;
    __syncthreads();
    if (tid < TPR && cont[tid]) bthr[tmpm0[tid * 64]] = tid;
    // zero A arrays (combine re-zeroes them each iteration thereafter)
    for (int idx = tid; idx < R * 132; idx += NTHR) {
        sm[OFF_A0 + idx] = 0.f;
        sm[OFF_A1 + idx] = 0.f;
    }
    __syncthreads();

    const bool cB = cont[t] != 0;
    float2 buf[NPAIR];
    #pragma unroll
    for (int p = 0; p < NPAIR; ++p) buf[p] = make_float2(0.f, 0.f);

    // sweep0: accumulate partials from initial spec (no update)
    sweep<false>(sm, r, t, cB, buf);
    __syncthreads();
    combine(sm, tid);
    __syncthreads();

    for (int it = 1; it <= NITER; ++it) {
        sweep<true>(sm, r, t, cB, buf);
        __syncthreads();
        if (it < NITER) {
            combine(sm, tid);
            __syncthreads();
        }
    }

    // ---- output: out[b][f][t0..t0+15]; f=1024 is provably static (fb row zero) ----
    for (int f = tid; f < N_STFT; f += NTHR) {
        float v[R];
        if (f < NF) {
            int pos = (((f & 63) >> 1) * TPR + (f >> 6)) * 2 + (f & 1);
            #pragma unroll
            for (int j = 0; j < R; ++j) v[j] = sm[OFF_SPEC + j * 1024 + pos];
        } else {
            #pragma unroll
            for (int j = 0; j < R; ++j)
                v[j] = spec_init[(size_t)(row0 + j) * N_STFT + 1024];
        }
        float* op = out + ((size_t)b * N_STFT + f) * NTIME + t0;
        #pragma unroll
        for (int j = 0; j < R; j += 4)
            *(float4*)&op[j] = make_float4(v[j], v[j + 1], v[j + 2], v[j + 3]);
    }
}

extern "C" void kernel_launch(void* const* d_in, const int* in_sizes, int n_in,
                              void* d_out, int out_size)
{
    const float* mel_in    = (const float*)d_in[0];  // (4,128,1024)
    const float* spec_init = (const float*)d_in[1];  // (4,1024,1025)
    const float* fb        = (const float*)d_in[2];  // (1025,128)
    float* out             = (float*)d_out;          // (4,1025,1024)

    size_t smem = SMEM_FLOATS * sizeof(float);
    cudaFuncSetAttribute(imel_kernel, cudaFuncAttributeMaxDynamicSharedMemorySize, (int)smem);
    imel_kernel<<<NCTAS, NTHR, smem>>>(mel_in, spec_init, fb, out);
}